// round 7
// baseline (speedup 1.0000x reference)
#include <cuda_runtime.h>
#include <cuda_bf16.h>
#include <math.h>
#include <cstdint>

#define N_NODES 200000
#define N_EDGES 1250000
#define N_GRAPHS 2048
#define IN_CH 128
#define HID 64
#define EMB 32

// ---------------- scratch (static device globals; no allocation) ----------------
__device__ int   g_is64;
__device__ int   g_deg[N_NODES];
__device__ float g_dis[N_NODES];
__device__ int   g_off[N_NODES];
__device__ int   g_cur[N_NODES];
__device__ int   g_csr[N_EDGES];
__device__ int   g_bsums[256];
__device__ __align__(16) float g_h1[(size_t)N_NODES * 64];   // GEMM output
__device__ __align__(16) float g_h2[(size_t)N_NODES * 64];   // AGG output / GEMM input
// bf16-split weight buffers (b[n][k] = bf16(W[k][n]) and residual)
__device__ __align__(16) __nv_bfloat16 g_wb0_1[64 * 128], g_wb1_1[64 * 128];
__device__ __align__(16) __nv_bfloat16 g_wb0_2[64 * 64],  g_wb1_2[64 * 64];
__device__ __align__(16) __nv_bfloat16 g_wb0_3[32 * 64],  g_wb1_3[32 * 64];

__device__ __forceinline__ long long load_idx(const void* p, long long i, int is64) {
    if (is64) return ((const long long*)p)[i];
    return (long long)((const int*)p)[i];
}

__device__ __forceinline__ uint32_t smem_to_u32(const void* smem_ptr) {
    uint32_t addr;
    asm("{ .reg .u64 tmp; cvta.to.shared.u64 tmp, %1; cvt.u32.u64 %0, tmp; }"
        : "=r"(addr) : "l"(smem_ptr));
    return addr;
}

__device__ __forceinline__ void ldsm4(uint32_t* r, uint32_t addr) {
    asm volatile("ldmatrix.sync.aligned.m8n8.x4.shared.b16 {%0,%1,%2,%3}, [%4];"
        : "=r"(r[0]), "=r"(r[1]), "=r"(r[2]), "=r"(r[3]) : "r"(addr));
}

__device__ __forceinline__ void mma16816(float* c, const uint32_t* a, uint32_t b0, uint32_t b1) {
    asm volatile(
        "mma.sync.aligned.m16n8k16.row.col.f32.bf16.bf16.f32 "
        "{%0,%1,%2,%3}, {%4,%5,%6,%7}, {%8,%9}, {%0,%1,%2,%3};"
        : "+f"(c[0]), "+f"(c[1]), "+f"(c[2]), "+f"(c[3])
        : "r"(a[0]), "r"(a[1]), "r"(a[2]), "r"(a[3]), "r"(b0), "r"(b1));
}

// ---------------- dtype detector ----------------
__global__ void k_detect(const unsigned* __restrict__ ei_words) {
    __shared__ int any_nonzero;
    if (threadIdx.x == 0) any_nonzero = 0;
    __syncthreads();
    unsigned w = ei_words[2 * threadIdx.x + 1];
    if (w != 0u) atomicOr(&any_nonzero, 1);
    __syncthreads();
    if (threadIdx.x == 0) g_is64 = any_nonzero ? 0 : 1;
}

// ---------------- W -> bf16 split converter (one block, W tiny) ----------------
template <int K, int NO>
__global__ void k_convert_w(const float* __restrict__ W,
                            __nv_bfloat16* __restrict__ wb0,
                            __nv_bfloat16* __restrict__ wb1) {
    for (int idx = threadIdx.x; idx < K * NO; idx += blockDim.x) {
        int c = idx / NO;     // k index (coalesced W read)
        int n = idx % NO;     // output channel
        float w = W[idx];
        __nv_bfloat16 h0 = __float2bfloat16(w);
        __nv_bfloat16 h1 = __float2bfloat16(w - __bfloat162float(h0));
        wb0[n * K + c] = h0;
        wb1[n * K + c] = h1;
    }
}

// ---------------- block inclusive scan ----------------
template <int NT>
__device__ __forceinline__ int block_inclusive_scan(int v, int tid) {
    int lane = tid & 31, w = tid >> 5;
    int x = v;
#pragma unroll
    for (int o = 1; o < 32; o <<= 1) {
        int y = __shfl_up_sync(0xffffffffu, x, o);
        if (lane >= o) x += y;
    }
    __shared__ int wsum[NT / 32];
    if (lane == 31) wsum[w] = x;
    __syncthreads();
    if (w == 0) {
        const int NW = NT / 32;
        int s = (lane < NW) ? wsum[lane] : 0;
#pragma unroll
        for (int o = 1; o < 32; o <<= 1) {
            int y = __shfl_up_sync(0xffffffffu, s, o);
            if (lane >= o) s += y;
        }
        if (lane < NW) wsum[lane] = s;
    }
    __syncthreads();
    return x + (w ? wsum[w - 1] : 0);
}

// ---------------- graph preprocessing ----------------
__global__ void k_zero_deg() {
    int i = blockIdx.x * 1024 + threadIdx.x;
    if (i < N_NODES) g_deg[i] = 0;
}

__global__ void k_count_deg(const void* __restrict__ ei) {
    int e = blockIdx.x * 256 + threadIdx.x;
    int is64 = g_is64;
    if (e < N_EDGES) {
        int d = (int)load_idx(ei, (long long)N_EDGES + e, is64);
        if (d >= 0 && d < N_NODES) atomicAdd(&g_deg[d], 1);
    }
}

__global__ void k_scan1() {
    int idx = blockIdx.x * 1024 + threadIdx.x;
    int v = (idx < N_NODES) ? g_deg[idx] : 0;
    int incl = block_inclusive_scan<1024>(v, threadIdx.x);
    if (idx < N_NODES) g_off[idx] = incl - v;
    if (threadIdx.x == 1023) g_bsums[blockIdx.x] = incl;
}

__global__ void k_scan2(int nb) {
    int v = ((int)threadIdx.x < nb) ? g_bsums[threadIdx.x] : 0;
    int incl = block_inclusive_scan<256>(v, threadIdx.x);
    if ((int)threadIdx.x < nb) g_bsums[threadIdx.x] = incl - v;
}

__global__ void k_scan3() {
    int idx = blockIdx.x * 256 + threadIdx.x;
    if (idx < N_NODES) {
        int o = g_off[idx] + g_bsums[idx >> 10];
        g_off[idx] = o;
        g_cur[idx] = o;
        g_dis[idx] = rsqrtf(1.0f + (float)g_deg[idx]);
    }
}

__global__ void k_fill_csr(const void* __restrict__ ei) {
    int e = blockIdx.x * 256 + threadIdx.x;
    int is64 = g_is64;
    if (e < N_EDGES) {
        int s = (int)load_idx(ei, e, is64);
        int d = (int)load_idx(ei, (long long)N_EDGES + e, is64);
        if (d >= 0 && d < N_NODES && s >= 0 && s < N_NODES) {
            int p = atomicAdd(&g_cur[d], 1);
            g_csr[p] = s;
        }
    }
}

// ---------------- HMMA bf16-split GEMM: g_h1[.,NO] = X[.,K] @ W[K,NO] ----------------
// BM=128 rows/CTA, 256 threads = 8 warps x 16 rows.
// X = a0+a1 (bf16 split, converted in-kernel), W^T = b0+b1 (pre-split in global).
// D = a0b0 + a1b0 + a0b1 in fp32. smem rows padded to SA=K+8 (ldmatrix conflict-free).
template <int K, int NO, bool EXT>
__global__ void __launch_bounds__(256) k_mma_gemm(const float* __restrict__ Xext,
                                                  const __nv_bfloat16* __restrict__ wb0,
                                                  const __nv_bfloat16* __restrict__ wb1,
                                                  int nrows) {
    constexpr int BM = 128;
    constexpr int SA = K + 8;
    constexpr int NT = NO / 8;    // n-tiles of 8
    constexpr int NKS = K / 16;   // k-steps of 16

    extern __shared__ char smem[];
    __nv_bfloat16* a0s = (__nv_bfloat16*)smem;
    __nv_bfloat16* a1s = a0s + BM * SA;
    __nv_bfloat16* b0s = a1s + BM * SA;
    __nv_bfloat16* b1s = b0s + NO * SA;

    const float* X = EXT ? Xext : (const float*)g_h2;
    float* Y = (float*)g_h1;

    const int tid = threadIdx.x;
    const int row0 = blockIdx.x * BM;

    // ---- convert A rows -> bf16 split (coalesced float2 reads) ----
#pragma unroll 4
    for (int idx = tid; idx < BM * (K / 2); idx += 256) {
        int r = idx / (K / 2);
        int c = (idx % (K / 2)) * 2;
        int gr = row0 + r;
        float2 v = make_float2(0.f, 0.f);
        if (gr < nrows) v = *(const float2*)(X + (size_t)gr * K + c);
        __nv_bfloat162 h0 = __floats2bfloat162_rn(v.x, v.y);
        __nv_bfloat162 h1 = __floats2bfloat162_rn(v.x - __bfloat162float(h0.x),
                                                  v.y - __bfloat162float(h0.y));
        *(uint32_t*)(a0s + r * SA + c) = *(uint32_t*)&h0;
        *(uint32_t*)(a1s + r * SA + c) = *(uint32_t*)&h1;
    }
    // ---- copy pre-split B from global (bf16, coalesced, L2-resident) ----
    {
        const uint32_t* w0 = (const uint32_t*)wb0;
        const uint32_t* w1 = (const uint32_t*)wb1;
#pragma unroll
        for (int p = tid; p < NO * (K / 2); p += 256) {
            int n = p / (K / 2);
            int c = (p % (K / 2)) * 2;
            *(uint32_t*)(b0s + n * SA + c) = w0[p];
            *(uint32_t*)(b1s + n * SA + c) = w1[p];
        }
    }
    __syncthreads();

    // ---- MMA mainloop ----
    const int wid = tid >> 5;
    const int lane = tid & 31;
    const int wr0 = wid * 16;
    const int lrow = lane & 7;
    const int sub = lane >> 3;

    float acc[NT][4];
#pragma unroll
    for (int t = 0; t < NT; t++)
#pragma unroll
        for (int q = 0; q < 4; q++) acc[t][q] = 0.0f;

    const uint32_t aBase0 = smem_to_u32(a0s);
    const uint32_t aBase1 = smem_to_u32(a1s);
    const uint32_t bBase0 = smem_to_u32(b0s);
    const uint32_t bBase1 = smem_to_u32(b1s);

    const uint32_t aoff = (uint32_t)(((wr0 + lrow + (sub & 1) * 8) * SA + (sub >> 1) * 8) * 2);
    const uint32_t boff_base = (uint32_t)(((lrow + (sub >> 1) * 8) * SA + (sub & 1) * 8) * 2);

#pragma unroll
    for (int ks = 0; ks < NKS; ks++) {
        uint32_t a0f[4], a1f[4];
        ldsm4(a0f, aBase0 + aoff + ks * 32);
        ldsm4(a1f, aBase1 + aoff + ks * 32);
#pragma unroll
        for (int p = 0; p < NT / 2; p++) {
            uint32_t boff = boff_base + (uint32_t)(p * 16 * SA * 2) + ks * 32;
            uint32_t b0f[4], b1f[4];
            ldsm4(b0f, bBase0 + boff);
            ldsm4(b1f, bBase1 + boff);
            mma16816(acc[2 * p],     a0f, b0f[0], b0f[1]);
            mma16816(acc[2 * p],     a1f, b0f[0], b0f[1]);
            mma16816(acc[2 * p],     a0f, b1f[0], b1f[1]);
            mma16816(acc[2 * p + 1], a0f, b0f[2], b0f[3]);
            mma16816(acc[2 * p + 1], a1f, b0f[2], b0f[3]);
            mma16816(acc[2 * p + 1], a0f, b1f[2], b1f[3]);
        }
    }

    // ---- epilogue: D[row=lane/4 (+8)][col=nt*8 + (lane%4)*2 (+1)] ----
    const int r = row0 + wr0 + (lane >> 2);
    const int cb = (lane & 3) * 2;
#pragma unroll
    for (int nt = 0; nt < NT; nt++) {
        if (r < nrows)
            *(float2*)(Y + (size_t)r * NO + nt * 8 + cb) = make_float2(acc[nt][0], acc[nt][1]);
        if (r + 8 < nrows)
            *(float2*)(Y + (size_t)(r + 8) * NO + nt * 8 + cb) = make_float2(acc[nt][2], acc[nt][3]);
    }
}

// ---------------- aggregation ----------------
template <int NO>
__global__ void k_agg(const float* __restrict__ b) {
    int warp = (blockIdx.x * blockDim.x + threadIdx.x) >> 5;
    int lane = threadIdx.x & 31;
    if (warp >= N_NODES) return;
    const float* hin = (const float*)g_h1;
    float* hout = (float*)g_h2;

    int i = warp;
    float di = g_dis[i];
    int start = g_off[i];
    int cnt = g_deg[i];

    float a0 = 0.f, a1 = 0.f, b0 = 0.f, b1 = 0.f;
    int j = 0;
    for (; j + 2 <= cnt; j += 2) {
        int s0 = g_csr[start + j];
        int s1 = g_csr[start + j + 1];
        float f0 = g_dis[s0];
        float f1 = g_dis[s1];
        const float* h0 = hin + (size_t)s0 * NO;
        const float* h1p = hin + (size_t)s1 * NO;
        a0 += f0 * h0[lane];
        b0 += f1 * h1p[lane];
        if (NO == 64) {
            a1 += f0 * h0[lane + 32];
            b1 += f1 * h1p[lane + 32];
        }
    }
    if (j < cnt) {
        int s0 = g_csr[start + j];
        float f0 = g_dis[s0];
        const float* h0 = hin + (size_t)s0 * NO;
        a0 += f0 * h0[lane];
        if (NO == 64) a1 += f0 * h0[lane + 32];
    }
    a0 += b0; a1 += b1;

    const float* hi = hin + (size_t)i * NO;
    float o0 = di * a0 + di * di * hi[lane] + b[lane];
    hout[(size_t)i * NO + lane] = fmaxf(o0, 0.0f);
    if (NO == 64) {
        float o1 = di * a1 + di * di * hi[lane + 32] + b[lane + 32];
        hout[(size_t)i * NO + lane + 32] = fmaxf(o1, 0.0f);
    }
}

// ---------------- pool + classifier (batch sorted) ----------------
__device__ __forceinline__ int lowerb(const void* a, int n, long long key, int is64) {
    int lo = 0, hi = n;
    while (lo < hi) {
        int mid = (lo + hi) >> 1;
        if (load_idx(a, mid, is64) < key) lo = mid + 1; else hi = mid;
    }
    return lo;
}

__global__ void k_pool(const void* __restrict__ batch,
                       const float* __restrict__ Wc1, const float* __restrict__ bc1,
                       const float* __restrict__ Wc2, const float* __restrict__ bc2,
                       float* __restrict__ out) {
    int warp = (blockIdx.x * blockDim.x + threadIdx.x) >> 5;
    int lane = threadIdx.x & 31;
    int wl = (threadIdx.x >> 5);
    if (warp >= N_GRAPHS) return;
    const float* h3 = (const float*)g_h2;
    int is64 = g_is64;

    long long g = warp;
    int start = lowerb(batch, N_NODES, g, is64);
    int end = lowerb(batch, N_NODES, g + 1, is64);

    float acc = 0.0f;
    for (int r = start; r < end; r++) acc += h3[(size_t)r * EMB + lane];
    float cnt = (float)(end - start);
    float emb = acc / fmaxf(cnt, 1.0f);

    __shared__ float sh[8][EMB];
    sh[wl][lane] = emb;
    __syncwarp();

    float partial = 0.0f;
    if (lane < 16) {
        float t = bc1[lane];
#pragma unroll
        for (int c = 0; c < EMB; c++) t = fmaf(sh[wl][c], Wc1[c * 16 + lane], t);
        t = fmaxf(t, 0.0f);
        partial = t * Wc2[lane];
    }
#pragma unroll
    for (int o = 8; o > 0; o >>= 1) partial += __shfl_down_sync(0xffffffffu, partial, o);
    if (lane == 0) out[g] = partial + bc2[0];
}

// ---------------- launch ----------------
template <int K, int NO, bool EXT>
static void launch_mma_gemm(const float* X, const __nv_bfloat16* wb0,
                            const __nv_bfloat16* wb1, int nrows, int blks) {
    constexpr int SMEM = (2 * 128 * (K + 8) + 2 * NO * (K + 8)) * 2;
    if (SMEM > 48 * 1024) {
        cudaFuncSetAttribute(k_mma_gemm<K, NO, EXT>,
                             cudaFuncAttributeMaxDynamicSharedMemorySize, SMEM);
    }
    k_mma_gemm<K, NO, EXT><<<blks, 256, SMEM>>>(X, wb0, wb1, nrows);
}

extern "C" void kernel_launch(void* const* d_in, const int* in_sizes, int n_in,
                              void* d_out, int out_size) {
    const float* x     = (const float*)d_in[0];
    const void*  ei    = d_in[1];
    const void*  batch = d_in[2];
    const float* W1 = (const float*)d_in[3];  const float* b1 = (const float*)d_in[4];
    const float* W2 = (const float*)d_in[5];  const float* b2 = (const float*)d_in[6];
    const float* W3 = (const float*)d_in[7];  const float* b3 = (const float*)d_in[8];
    const float* Wc1 = (const float*)d_in[9]; const float* bc1 = (const float*)d_in[10];
    const float* Wc2 = (const float*)d_in[11]; const float* bc2 = (const float*)d_in[12];
    float* out = (float*)d_out;

    const int NB_N1024 = (N_NODES + 1023) / 1024;
    const int NB_E256  = (N_EDGES + 255) / 256;
    const int NB_N256  = (N_NODES + 255) / 256;

    // weight conversion (tiny, once per call)
    k_convert_w<128, 64><<<1, 256>>>(W1, g_wb0_1, g_wb1_1);
    k_convert_w<64, 64><<<1, 256>>>(W2, g_wb0_2, g_wb1_2);
    k_convert_w<64, 32><<<1, 256>>>(W3, g_wb0_3, g_wb1_3);

    k_detect<<<1, 128>>>((const unsigned*)ei);
    k_zero_deg<<<NB_N1024, 1024>>>();
    k_count_deg<<<NB_E256, 256>>>(ei);
    k_scan1<<<NB_N1024, 1024>>>();
    k_scan2<<<1, 256>>>(NB_N1024);
    k_scan3<<<NB_N256, 256>>>();
    k_fill_csr<<<NB_E256, 256>>>(ei);

    const int GEMM_BLKS = (N_NODES + 127) / 128;        // 1563
    const int AGG_BLKS  = (N_NODES * 32 + 255) / 256;   // 25000

    // layer 1: 128 -> 64  (x -> g_h1 -> g_h2)
    launch_mma_gemm<128, 64, true>(x, g_wb0_1, g_wb1_1, N_NODES, GEMM_BLKS);
    k_agg<64><<<AGG_BLKS, 256>>>(b1);
    // layer 2: 64 -> 64   (g_h2 -> g_h1 -> g_h2)
    launch_mma_gemm<64, 64, false>(nullptr, g_wb0_2, g_wb1_2, N_NODES, GEMM_BLKS);
    k_agg<64><<<AGG_BLKS, 256>>>(b2);
    // layer 3: 64 -> 32   (g_h2 -> g_h1 -> g_h2)
    launch_mma_gemm<64, 32, false>(nullptr, g_wb0_3, g_wb1_3, N_NODES, GEMM_BLKS);
    k_agg<32><<<AGG_BLKS, 256>>>(b3);

    // pool + classifier
    k_pool<<<N_GRAPHS / 8, 256>>>(batch, Wc1, bc1, Wc2, bc2, out);
}

// round 8
// speedup vs baseline: 1.4774x; 1.4774x over previous
#include <cuda_runtime.h>
#include <math.h>

#define N_NODES 200000
#define N_EDGES 1250000
#define N_GRAPHS 2048
#define IN_CH 128
#define HID 64
#define EMB 32

// ---------------- scratch (static device globals; no allocation) ----------------
__device__ int   g_is64;
__device__ int   g_deg[N_NODES];
__device__ float g_dis[N_NODES];
__device__ int   g_off[N_NODES];
__device__ int   g_cur[N_NODES];
__device__ int   g_csr[N_EDGES];
__device__ int   g_bsums[256];
__device__ __align__(16) float g_h1[(size_t)N_NODES * 64];   // GEMM output
__device__ __align__(16) float g_h2[(size_t)N_NODES * 64];   // AGG output / GEMM input

__device__ __forceinline__ long long load_idx(const void* p, long long i, int is64) {
    if (is64) return ((const long long*)p)[i];
    return (long long)((const int*)p)[i];
}

// ---------------- zero degree + dtype detect (fused) ----------------
__global__ void k_zero_detect(const unsigned* __restrict__ ei_words) {
    int i = blockIdx.x * 1024 + threadIdx.x;
    if (i < N_NODES) g_deg[i] = 0;
    if (blockIdx.x == 0 && threadIdx.x < 128) {
        // int64 nonneg < 2^31  =>  odd 32-bit words are all zero
        unsigned w = ei_words[2 * threadIdx.x + 1];
        unsigned any = __ballot_sync(0xffffffffu, w != 0u);
        unsigned combined = any;
        // combine across the 4 warps via shared
        __shared__ unsigned s_any[4];
        if ((threadIdx.x & 31) == 0) s_any[threadIdx.x >> 5] = combined;
        __syncthreads();
        if (threadIdx.x == 0) {
            unsigned t = s_any[0] | s_any[1] | s_any[2] | s_any[3];
            g_is64 = t ? 0 : 1;
        }
    }
}

// ---------------- block inclusive scan ----------------
template <int NT>
__device__ __forceinline__ int block_inclusive_scan(int v, int tid) {
    int lane = tid & 31, w = tid >> 5;
    int x = v;
#pragma unroll
    for (int o = 1; o < 32; o <<= 1) {
        int y = __shfl_up_sync(0xffffffffu, x, o);
        if (lane >= o) x += y;
    }
    __shared__ int wsum[NT / 32];
    if (lane == 31) wsum[w] = x;
    __syncthreads();
    if (w == 0) {
        const int NW = NT / 32;
        int s = (lane < NW) ? wsum[lane] : 0;
#pragma unroll
        for (int o = 1; o < 32; o <<= 1) {
            int y = __shfl_up_sync(0xffffffffu, s, o);
            if (lane >= o) s += y;
        }
        if (lane < NW) wsum[lane] = s;
    }
    __syncthreads();
    return x + (w ? wsum[w - 1] : 0);
}

// ---------------- graph preprocessing ----------------
__global__ void k_count_deg(const void* __restrict__ ei) {
    int e = blockIdx.x * 256 + threadIdx.x;
    int is64 = g_is64;
    if (e < N_EDGES) {
        int d = (int)load_idx(ei, (long long)N_EDGES + e, is64);
        if (d >= 0 && d < N_NODES) atomicAdd(&g_deg[d], 1);
    }
}

__global__ void k_scan1() {
    int idx = blockIdx.x * 1024 + threadIdx.x;
    int v = (idx < N_NODES) ? g_deg[idx] : 0;
    int incl = block_inclusive_scan<1024>(v, threadIdx.x);
    if (idx < N_NODES) g_off[idx] = incl - v;
    if (threadIdx.x == 1023) g_bsums[blockIdx.x] = incl;
}

__global__ void k_scan2(int nb) {
    int v = ((int)threadIdx.x < nb) ? g_bsums[threadIdx.x] : 0;
    int incl = block_inclusive_scan<256>(v, threadIdx.x);
    if ((int)threadIdx.x < nb) g_bsums[threadIdx.x] = incl - v;
}

__global__ void k_scan3() {
    int idx = blockIdx.x * 256 + threadIdx.x;
    if (idx < N_NODES) {
        int o = g_off[idx] + g_bsums[idx >> 10];
        g_off[idx] = o;
        g_cur[idx] = o;
        g_dis[idx] = rsqrtf(1.0f + (float)g_deg[idx]);
    }
}

__global__ void k_fill_csr(const void* __restrict__ ei) {
    int e = blockIdx.x * 256 + threadIdx.x;
    int is64 = g_is64;
    if (e < N_EDGES) {
        int s = (int)load_idx(ei, e, is64);
        int d = (int)load_idx(ei, (long long)N_EDGES + e, is64);
        if (d >= 0 && d < N_NODES && s >= 0 && s < N_NODES) {
            int p = atomicAdd(&g_cur[d], 1);
            g_csr[p] = s;
        }
    }
}

// ---------------- tiled fp32 GEMM: g_h1[nrows,NO] = X[nrows,K] @ W[K,NO] ----------------
// BM=128 rows/block, BK=64, 256 threads, 8 x (NO/16) micro-tile per thread.  (R4 proven)
template <int K, int NO, bool EXT>
__global__ void __launch_bounds__(256) k_gemm(const float* __restrict__ Xext,
                                              const float* __restrict__ W, int nrows) {
    constexpr int BM = 128, BK = 64;
    constexpr int TN = NO / 16;  // 4 for NO=64, 2 for NO=32
    constexpr int NKC = K / BK;
    __shared__ float xs[BK][BM];
    __shared__ float ws[BK][NO];

    const float* X = EXT ? Xext : (const float*)g_h2;
    float* Y = (float*)g_h1;

    const int tid = threadIdx.x;
    const int tr = tid >> 4;
    const int tc = tid & 15;
    const int row0 = blockIdx.x * BM;

    const int lr = tid & 127;
    const int lhalf = tid >> 7;
    const int gr_load = row0 + lr;
    const bool ld_ok = (gr_load < nrows);
    const float4* Xr = (const float4*)(X + (size_t)gr_load * K);

    float acc[8][TN];
#pragma unroll
    for (int i = 0; i < 8; i++)
#pragma unroll
        for (int j = 0; j < TN; j++) acc[i][j] = 0.0f;

#pragma unroll
    for (int kc = 0; kc < NKC; kc++) {
        if (kc > 0) __syncthreads();
#pragma unroll
        for (int t = 0; t < 8; t++) {
            int c4 = lhalf * 8 + t;
            float4 v = ld_ok ? Xr[kc * (BK / 4) + c4] : make_float4(0.f, 0.f, 0.f, 0.f);
            int k0 = c4 * 4;
            xs[k0 + 0][lr] = v.x; xs[k0 + 1][lr] = v.y;
            xs[k0 + 2][lr] = v.z; xs[k0 + 3][lr] = v.w;
        }
        {
            const float4* W4 = (const float4*)(W + (size_t)kc * BK * NO);
            float4* ws4 = (float4*)ws;
#pragma unroll
            for (int t = tid; t < BK * NO / 4; t += 256) ws4[t] = W4[t];
        }
        __syncthreads();

#pragma unroll 8
        for (int k = 0; k < BK; k++) {
            float xv[8];
            *(float4*)&xv[0] = *(const float4*)&xs[k][tr * 8];
            *(float4*)&xv[4] = *(const float4*)&xs[k][tr * 8 + 4];
            float wv[TN];
            if (TN == 4) {
                *(float4*)&wv[0] = *(const float4*)&ws[k][tc * 4];
            } else {
                *(float2*)&wv[0] = *(const float2*)&ws[k][tc * 2];
            }
#pragma unroll
            for (int i = 0; i < 8; i++)
#pragma unroll
                for (int j = 0; j < TN; j++) acc[i][j] = fmaf(xv[i], wv[j], acc[i][j]);
        }
    }

#pragma unroll
    for (int i = 0; i < 8; i++) {
        int r = row0 + tr * 8 + i;
        if (r < nrows) {
            if (TN == 4) {
                float4 o = make_float4(acc[i][0], acc[i][1], acc[i][2], acc[i][3]);
                *reinterpret_cast<float4*>(&Y[(size_t)r * NO + tc * 4]) = o;
            } else {
                float2 o = make_float2(acc[i][0], acc[i][1]);
                *reinterpret_cast<float2*>(&Y[(size_t)r * NO + tc * 2]) = o;
            }
        }
    }
}

// ---------------- aggregation: g_h2[i] = relu(di*sum_j dis[s]*h[s] + di^2*h[i] + b) ----------------
// NO=64: lane owns channels (2*lane, 2*lane+1) -> single LDG.64 per edge row.
__global__ void k_agg64(const float* __restrict__ b) {
    int warp = (blockIdx.x * blockDim.x + threadIdx.x) >> 5;
    int lane = threadIdx.x & 31;
    if (warp >= N_NODES) return;
    const float* hin = (const float*)g_h1;
    float* hout = (float*)g_h2;

    int i = warp;
    float di = g_dis[i];
    int start = g_off[i];
    int cnt = g_deg[i];

    float ax = 0.f, ay = 0.f, bx = 0.f, by = 0.f;
    int j = 0;
    for (; j + 2 <= cnt; j += 2) {
        int s0 = __ldg(&g_csr[start + j]);
        int s1 = __ldg(&g_csr[start + j + 1]);
        float f0 = __ldg(&g_dis[s0]);
        float f1 = __ldg(&g_dis[s1]);
        float2 v0 = *(const float2*)(hin + (size_t)s0 * 64 + 2 * lane);
        float2 v1 = *(const float2*)(hin + (size_t)s1 * 64 + 2 * lane);
        ax = fmaf(f0, v0.x, ax); ay = fmaf(f0, v0.y, ay);
        bx = fmaf(f1, v1.x, bx); by = fmaf(f1, v1.y, by);
    }
    if (j < cnt) {
        int s0 = __ldg(&g_csr[start + j]);
        float f0 = __ldg(&g_dis[s0]);
        float2 v0 = *(const float2*)(hin + (size_t)s0 * 64 + 2 * lane);
        ax = fmaf(f0, v0.x, ax); ay = fmaf(f0, v0.y, ay);
    }
    ax += bx; ay += by;

    float2 hi = *(const float2*)(hin + (size_t)i * 64 + 2 * lane);
    float2 bb = *(const float2*)(b + 2 * lane);
    float dii = di * di;
    float ox = fmaf(di, ax, fmaf(dii, hi.x, bb.x));
    float oy = fmaf(di, ay, fmaf(dii, hi.y, bb.y));
    *(float2*)(hout + (size_t)i * 64 + 2 * lane) = make_float2(fmaxf(ox, 0.f), fmaxf(oy, 0.f));
}

// NO=32: lane owns channel lane.
__global__ void k_agg32(const float* __restrict__ b) {
    int warp = (blockIdx.x * blockDim.x + threadIdx.x) >> 5;
    int lane = threadIdx.x & 31;
    if (warp >= N_NODES) return;
    const float* hin = (const float*)g_h1;
    float* hout = (float*)g_h2;

    int i = warp;
    float di = g_dis[i];
    int start = g_off[i];
    int cnt = g_deg[i];

    float a0 = 0.f, b0 = 0.f;
    int j = 0;
    for (; j + 2 <= cnt; j += 2) {
        int s0 = __ldg(&g_csr[start + j]);
        int s1 = __ldg(&g_csr[start + j + 1]);
        float f0 = __ldg(&g_dis[s0]);
        float f1 = __ldg(&g_dis[s1]);
        a0 = fmaf(f0, hin[(size_t)s0 * 32 + lane], a0);
        b0 = fmaf(f1, hin[(size_t)s1 * 32 + lane], b0);
    }
    if (j < cnt) {
        int s0 = __ldg(&g_csr[start + j]);
        float f0 = __ldg(&g_dis[s0]);
        a0 = fmaf(f0, hin[(size_t)s0 * 32 + lane], a0);
    }
    a0 += b0;

    float o0 = fmaf(di, a0, fmaf(di * di, hin[(size_t)i * 32 + lane], b[lane]));
    hout[(size_t)i * 32 + lane] = fmaxf(o0, 0.0f);
}

// ---------------- pool + classifier (batch sorted) ----------------
__device__ __forceinline__ int lowerb(const void* a, int n, long long key, int is64) {
    int lo = 0, hi = n;
    while (lo < hi) {
        int mid = (lo + hi) >> 1;
        if (load_idx(a, mid, is64) < key) lo = mid + 1; else hi = mid;
    }
    return lo;
}

__global__ void k_pool(const void* __restrict__ batch,
                       const float* __restrict__ Wc1, const float* __restrict__ bc1,
                       const float* __restrict__ Wc2, const float* __restrict__ bc2,
                       float* __restrict__ out) {
    int warp = (blockIdx.x * blockDim.x + threadIdx.x) >> 5;
    int lane = threadIdx.x & 31;
    int wl = (threadIdx.x >> 5);
    if (warp >= N_GRAPHS) return;
    const float* h3 = (const float*)g_h2;
    int is64 = g_is64;

    long long g = warp;
    int start = lowerb(batch, N_NODES, g, is64);
    int end = lowerb(batch, N_NODES, g + 1, is64);

    float acc = 0.0f;
    for (int r = start; r < end; r++) acc += h3[(size_t)r * EMB + lane];
    float cnt = (float)(end - start);
    float emb = acc / fmaxf(cnt, 1.0f);

    __shared__ float sh[8][EMB];
    sh[wl][lane] = emb;
    __syncwarp();

    float partial = 0.0f;
    if (lane < 16) {
        float t = bc1[lane];
#pragma unroll
        for (int c = 0; c < EMB; c++) t = fmaf(sh[wl][c], Wc1[c * 16 + lane], t);
        t = fmaxf(t, 0.0f);
        partial = t * Wc2[lane];
    }
#pragma unroll
    for (int o = 8; o > 0; o >>= 1) partial += __shfl_down_sync(0xffffffffu, partial, o);
    if (lane == 0) out[g] = partial + bc2[0];
}

// ---------------- launch ----------------
extern "C" void kernel_launch(void* const* d_in, const int* in_sizes, int n_in,
                              void* d_out, int out_size) {
    const float* x     = (const float*)d_in[0];
    const void*  ei    = d_in[1];
    const void*  batch = d_in[2];
    const float* W1 = (const float*)d_in[3];  const float* b1 = (const float*)d_in[4];
    const float* W2 = (const float*)d_in[5];  const float* b2 = (const float*)d_in[6];
    const float* W3 = (const float*)d_in[7];  const float* b3 = (const float*)d_in[8];
    const float* Wc1 = (const float*)d_in[9]; const float* bc1 = (const float*)d_in[10];
    const float* Wc2 = (const float*)d_in[11]; const float* bc2 = (const float*)d_in[12];
    float* out = (float*)d_out;

    const int NB_N1024 = (N_NODES + 1023) / 1024;   // 196
    const int NB_E256  = (N_EDGES + 255) / 256;     // 4883
    const int NB_N256  = (N_NODES + 255) / 256;

    k_zero_detect<<<NB_N1024, 1024>>>((const unsigned*)ei);
    k_count_deg<<<NB_E256, 256>>>(ei);
    k_scan1<<<NB_N1024, 1024>>>();
    k_scan2<<<1, 256>>>(NB_N1024);
    k_scan3<<<NB_N256, 256>>>();
    k_fill_csr<<<NB_E256, 256>>>(ei);

    const int GEMM_BLKS = (N_NODES + 127) / 128;        // 1563
    const int AGG_BLKS  = (N_NODES * 32 + 255) / 256;   // 25000

    // layer 1: 128 -> 64  (x -> g_h1 -> g_h2)
    k_gemm<128, 64, true><<<GEMM_BLKS, 256>>>(x, W1, N_NODES);
    k_agg64<<<AGG_BLKS, 256>>>(b1);
    // layer 2: 64 -> 64   (g_h2 -> g_h1 -> g_h2)
    k_gemm<64, 64, false><<<GEMM_BLKS, 256>>>(nullptr, W2, N_NODES);
    k_agg64<<<AGG_BLKS, 256>>>(b2);
    // layer 3: 64 -> 32   (g_h2 -> g_h1 -> g_h2)
    k_gemm<64, 32, false><<<GEMM_BLKS, 256>>>(nullptr, W3, N_NODES);
    k_agg32<<<AGG_BLKS, 256>>>(b3);

    // pool + classifier
    k_pool<<<N_GRAPHS / 8, 256>>>(batch, Wc1, bc1, Wc2, bc2, out);
}

// round 9
// speedup vs baseline: 1.5117x; 1.0232x over previous
#include <cuda_runtime.h>
#include <math.h>
#include <cstdint>

#define N_NODES 200000
#define N_EDGES 1250000
#define N_GRAPHS 2048
#define IN_CH 128
#define HID 64
#define EMB 32

// ---------------- scratch (static device globals; no allocation) ----------------
__device__ int   g_is64;
__device__ int   g_deg[N_NODES];
__device__ float g_dis[N_NODES];
__device__ int   g_off[N_NODES];
__device__ int   g_cur[N_NODES];
__device__ int   g_csr[N_EDGES];
__device__ int   g_bsums[256];
__device__ __align__(16) float g_h1[(size_t)N_NODES * 64];   // GEMM output
__device__ __align__(16) float g_h2[(size_t)N_NODES * 64];   // AGG output / GEMM input

__device__ __forceinline__ long long load_idx(const void* p, long long i, int is64) {
    if (is64) return ((const long long*)p)[i];
    return (long long)((const int*)p)[i];
}

// ---------------- zero degree + dtype detect (fused) ----------------
__global__ void k_zero_detect(const unsigned* __restrict__ ei_words) {
    int i = blockIdx.x * 1024 + threadIdx.x;
    if (i < N_NODES) g_deg[i] = 0;
    if (blockIdx.x == 0 && threadIdx.x < 128) {
        unsigned w = ei_words[2 * threadIdx.x + 1];
        unsigned any = __ballot_sync(0xffffffffu, w != 0u);
        __shared__ unsigned s_any[4];
        if ((threadIdx.x & 31) == 0) s_any[threadIdx.x >> 5] = any;
        __syncthreads();
        if (threadIdx.x == 0) {
            unsigned t = s_any[0] | s_any[1] | s_any[2] | s_any[3];
            g_is64 = t ? 0 : 1;
        }
    }
}

// ---------------- block inclusive scan ----------------
template <int NT>
__device__ __forceinline__ int block_inclusive_scan(int v, int tid) {
    int lane = tid & 31, w = tid >> 5;
    int x = v;
#pragma unroll
    for (int o = 1; o < 32; o <<= 1) {
        int y = __shfl_up_sync(0xffffffffu, x, o);
        if (lane >= o) x += y;
    }
    __shared__ int wsum[NT / 32];
    if (lane == 31) wsum[w] = x;
    __syncthreads();
    if (w == 0) {
        const int NW = NT / 32;
        int s = (lane < NW) ? wsum[lane] : 0;
#pragma unroll
        for (int o = 1; o < 32; o <<= 1) {
            int y = __shfl_up_sync(0xffffffffu, s, o);
            if (lane >= o) s += y;
        }
        if (lane < NW) wsum[lane] = s;
    }
    __syncthreads();
    return x + (w ? wsum[w - 1] : 0);
}

// ---------------- graph preprocessing ----------------
__global__ void k_count_deg(const void* __restrict__ ei) {
    int e = blockIdx.x * 256 + threadIdx.x;
    int is64 = g_is64;
    if (e < N_EDGES) {
        int d = (int)load_idx(ei, (long long)N_EDGES + e, is64);
        if (d >= 0 && d < N_NODES) atomicAdd(&g_deg[d], 1);
    }
}

__global__ void k_scan1() {
    int idx = blockIdx.x * 1024 + threadIdx.x;
    int v = (idx < N_NODES) ? g_deg[idx] : 0;
    int incl = block_inclusive_scan<1024>(v, threadIdx.x);
    if (idx < N_NODES) g_off[idx] = incl - v;
    if (threadIdx.x == 1023) g_bsums[blockIdx.x] = incl;
}

__global__ void k_scan2(int nb) {
    int v = ((int)threadIdx.x < nb) ? g_bsums[threadIdx.x] : 0;
    int incl = block_inclusive_scan<256>(v, threadIdx.x);
    if ((int)threadIdx.x < nb) g_bsums[threadIdx.x] = incl - v;
}

__global__ void k_scan3() {
    int idx = blockIdx.x * 256 + threadIdx.x;
    if (idx < N_NODES) {
        int o = g_off[idx] + g_bsums[idx >> 10];
        g_off[idx] = o;
        g_cur[idx] = o;
        g_dis[idx] = rsqrtf(1.0f + (float)g_deg[idx]);
    }
}

__global__ void k_fill_csr(const void* __restrict__ ei) {
    int e = blockIdx.x * 256 + threadIdx.x;
    int is64 = g_is64;
    if (e < N_EDGES) {
        int s = (int)load_idx(ei, e, is64);
        int d = (int)load_idx(ei, (long long)N_EDGES + e, is64);
        if (d >= 0 && d < N_NODES && s >= 0 && s < N_NODES) {
            int p = atomicAdd(&g_cur[d], 1);
            g_csr[p] = s;
        }
    }
}

// ---------------- tiled fp32 GEMM with packed f32x2 FMA ----------------
// g_h1[nrows,NO] = X[nrows,K] @ W[K,NO].
// BM=128 rows/block, BK=64, 256 threads, 8 x (NO/16) micro-tile per thread.
// Accumulators packed across adjacent row pairs (b64 f32x2); x pairs come free
// from shared (consecutive rows contiguous); w broadcast-packed per k-iter.
template <int K, int NO, bool EXT>
__global__ void __launch_bounds__(256) k_gemm(const float* __restrict__ Xext,
                                              const float* __restrict__ W, int nrows) {
    constexpr int BM = 128, BK = 64;
    constexpr int TN = NO / 16;  // 4 for NO=64, 2 for NO=32
    constexpr int NKC = K / BK;
    __shared__ float xs[BK][BM];
    __shared__ float ws[BK][NO];

    const float* X = EXT ? Xext : (const float*)g_h2;
    float* Y = (float*)g_h1;

    const int tid = threadIdx.x;
    const int tr = tid >> 4;
    const int tc = tid & 15;
    const int row0 = blockIdx.x * BM;

    const int lr = tid & 127;
    const int lhalf = tid >> 7;
    const int gr_load = row0 + lr;
    const bool ld_ok = (gr_load < nrows);
    const float4* Xr = (const float4*)(X + (size_t)gr_load * K);

    // packed accumulators: acc2[p][j] = {row 2p, row 2p+1} for column tc*TN+j
    uint64_t acc2[4][TN];
#pragma unroll
    for (int p = 0; p < 4; p++)
#pragma unroll
        for (int j = 0; j < TN; j++) acc2[p][j] = 0ull;

#pragma unroll
    for (int kc = 0; kc < NKC; kc++) {
        if (kc > 0) __syncthreads();
#pragma unroll
        for (int t = 0; t < 8; t++) {
            int c4 = lhalf * 8 + t;
            float4 v = ld_ok ? Xr[kc * (BK / 4) + c4] : make_float4(0.f, 0.f, 0.f, 0.f);
            int k0 = c4 * 4;
            xs[k0 + 0][lr] = v.x; xs[k0 + 1][lr] = v.y;
            xs[k0 + 2][lr] = v.z; xs[k0 + 3][lr] = v.w;
        }
        {
            const float4* W4 = (const float4*)(W + (size_t)kc * BK * NO);
            float4* ws4 = (float4*)ws;
#pragma unroll
            for (int t = tid; t < BK * NO / 4; t += 256) ws4[t] = W4[t];
        }
        __syncthreads();

#pragma unroll 8
        for (int k = 0; k < BK; k++) {
            // x row-pairs: 2 x LDS.128 reinterpreted as 4 packed f32x2
            ulonglong2 xlo = *(const ulonglong2*)&xs[k][tr * 8];
            ulonglong2 xhi = *(const ulonglong2*)&xs[k][tr * 8 + 4];
            uint64_t xp[4] = {xlo.x, xlo.y, xhi.x, xhi.y};
            // w values + broadcast packs
            float wv[TN];
            if (TN == 4) {
                *(float4*)&wv[0] = *(const float4*)&ws[k][tc * 4];
            } else {
                *(float2*)&wv[0] = *(const float2*)&ws[k][tc * 2];
            }
            uint64_t wp[TN];
#pragma unroll
            for (int j = 0; j < TN; j++) {
                unsigned wb = __float_as_uint(wv[j]);
                asm("mov.b64 %0, {%1, %1};" : "=l"(wp[j]) : "r"(wb));
            }
#pragma unroll
            for (int p = 0; p < 4; p++)
#pragma unroll
                for (int j = 0; j < TN; j++)
                    asm("fma.rn.f32x2 %0, %1, %2, %0;"
                        : "+l"(acc2[p][j]) : "l"(xp[p]), "l"(wp[j]));
        }
    }

    // unpack packed accumulators -> per-row values
    float acc[8][TN];
#pragma unroll
    for (int p = 0; p < 4; p++)
#pragma unroll
        for (int j = 0; j < TN; j++) {
            unsigned lo, hi;
            asm("mov.b64 {%0, %1}, %2;" : "=r"(lo), "=r"(hi) : "l"(acc2[p][j]));
            acc[2 * p][j] = __uint_as_float(lo);
            acc[2 * p + 1][j] = __uint_as_float(hi);
        }

#pragma unroll
    for (int i = 0; i < 8; i++) {
        int r = row0 + tr * 8 + i;
        if (r < nrows) {
            if (TN == 4) {
                float4 o = make_float4(acc[i][0], acc[i][1], acc[i][2], acc[i][3]);
                *reinterpret_cast<float4*>(&Y[(size_t)r * NO + tc * 4]) = o;
            } else {
                float2 o = make_float2(acc[i][0], acc[i][1]);
                *reinterpret_cast<float2*>(&Y[(size_t)r * NO + tc * 2]) = o;
            }
        }
    }
}

// ---------------- aggregation (R8 proven) ----------------
__global__ void k_agg64(const float* __restrict__ b) {
    int warp = (blockIdx.x * blockDim.x + threadIdx.x) >> 5;
    int lane = threadIdx.x & 31;
    if (warp >= N_NODES) return;
    const float* hin = (const float*)g_h1;
    float* hout = (float*)g_h2;

    int i = warp;
    float di = g_dis[i];
    int start = g_off[i];
    int cnt = g_deg[i];

    float ax = 0.f, ay = 0.f, bx = 0.f, by = 0.f;
    int j = 0;
    for (; j + 2 <= cnt; j += 2) {
        int s0 = __ldg(&g_csr[start + j]);
        int s1 = __ldg(&g_csr[start + j + 1]);
        float f0 = __ldg(&g_dis[s0]);
        float f1 = __ldg(&g_dis[s1]);
        float2 v0 = *(const float2*)(hin + (size_t)s0 * 64 + 2 * lane);
        float2 v1 = *(const float2*)(hin + (size_t)s1 * 64 + 2 * lane);
        ax = fmaf(f0, v0.x, ax); ay = fmaf(f0, v0.y, ay);
        bx = fmaf(f1, v1.x, bx); by = fmaf(f1, v1.y, by);
    }
    if (j < cnt) {
        int s0 = __ldg(&g_csr[start + j]);
        float f0 = __ldg(&g_dis[s0]);
        float2 v0 = *(const float2*)(hin + (size_t)s0 * 64 + 2 * lane);
        ax = fmaf(f0, v0.x, ax); ay = fmaf(f0, v0.y, ay);
    }
    ax += bx; ay += by;

    float2 hi = *(const float2*)(hin + (size_t)i * 64 + 2 * lane);
    float2 bb = *(const float2*)(b + 2 * lane);
    float dii = di * di;
    float ox = fmaf(di, ax, fmaf(dii, hi.x, bb.x));
    float oy = fmaf(di, ay, fmaf(dii, hi.y, bb.y));
    *(float2*)(hout + (size_t)i * 64 + 2 * lane) = make_float2(fmaxf(ox, 0.f), fmaxf(oy, 0.f));
}

__global__ void k_agg32(const float* __restrict__ b) {
    int warp = (blockIdx.x * blockDim.x + threadIdx.x) >> 5;
    int lane = threadIdx.x & 31;
    if (warp >= N_NODES) return;
    const float* hin = (const float*)g_h1;
    float* hout = (float*)g_h2;

    int i = warp;
    float di = g_dis[i];
    int start = g_off[i];
    int cnt = g_deg[i];

    float a0 = 0.f, b0 = 0.f;
    int j = 0;
    for (; j + 2 <= cnt; j += 2) {
        int s0 = __ldg(&g_csr[start + j]);
        int s1 = __ldg(&g_csr[start + j + 1]);
        float f0 = __ldg(&g_dis[s0]);
        float f1 = __ldg(&g_dis[s1]);
        a0 = fmaf(f0, hin[(size_t)s0 * 32 + lane], a0);
        b0 = fmaf(f1, hin[(size_t)s1 * 32 + lane], b0);
    }
    if (j < cnt) {
        int s0 = __ldg(&g_csr[start + j]);
        float f0 = __ldg(&g_dis[s0]);
        a0 = fmaf(f0, hin[(size_t)s0 * 32 + lane], a0);
    }
    a0 += b0;

    float o0 = fmaf(di, a0, fmaf(di * di, hin[(size_t)i * 32 + lane], b[lane]));
    hout[(size_t)i * 32 + lane] = fmaxf(o0, 0.0f);
}

// ---------------- pool + classifier (batch sorted) ----------------
__device__ __forceinline__ int lowerb(const void* a, int n, long long key, int is64) {
    int lo = 0, hi = n;
    while (lo < hi) {
        int mid = (lo + hi) >> 1;
        if (load_idx(a, mid, is64) < key) lo = mid + 1; else hi = mid;
    }
    return lo;
}

__global__ void k_pool(const void* __restrict__ batch,
                       const float* __restrict__ Wc1, const float* __restrict__ bc1,
                       const float* __restrict__ Wc2, const float* __restrict__ bc2,
                       float* __restrict__ out) {
    int warp = (blockIdx.x * blockDim.x + threadIdx.x) >> 5;
    int lane = threadIdx.x & 31;
    int wl = (threadIdx.x >> 5);
    if (warp >= N_GRAPHS) return;
    const float* h3 = (const float*)g_h2;
    int is64 = g_is64;

    long long g = warp;
    int start = lowerb(batch, N_NODES, g, is64);
    int end = lowerb(batch, N_NODES, g + 1, is64);

    float acc = 0.0f;
    for (int r = start; r < end; r++) acc += h3[(size_t)r * EMB + lane];
    float cnt = (float)(end - start);
    float emb = acc / fmaxf(cnt, 1.0f);

    __shared__ float sh[8][EMB];
    sh[wl][lane] = emb;
    __syncwarp();

    float partial = 0.0f;
    if (lane < 16) {
        float t = bc1[lane];
#pragma unroll
        for (int c = 0; c < EMB; c++) t = fmaf(sh[wl][c], Wc1[c * 16 + lane], t);
        t = fmaxf(t, 0.0f);
        partial = t * Wc2[lane];
    }
#pragma unroll
    for (int o = 8; o > 0; o >>= 1) partial += __shfl_down_sync(0xffffffffu, partial, o);
    if (lane == 0) out[g] = partial + bc2[0];
}

// ---------------- launch ----------------
extern "C" void kernel_launch(void* const* d_in, const int* in_sizes, int n_in,
                              void* d_out, int out_size) {
    const float* x     = (const float*)d_in[0];
    const void*  ei    = d_in[1];
    const void*  batch = d_in[2];
    const float* W1 = (const float*)d_in[3];  const float* b1 = (const float*)d_in[4];
    const float* W2 = (const float*)d_in[5];  const float* b2 = (const float*)d_in[6];
    const float* W3 = (const float*)d_in[7];  const float* b3 = (const float*)d_in[8];
    const float* Wc1 = (const float*)d_in[9]; const float* bc1 = (const float*)d_in[10];
    const float* Wc2 = (const float*)d_in[11]; const float* bc2 = (const float*)d_in[12];
    float* out = (float*)d_out;

    const int NB_N1024 = (N_NODES + 1023) / 1024;   // 196
    const int NB_E256  = (N_EDGES + 255) / 256;     // 4883
    const int NB_N256  = (N_NODES + 255) / 256;

    k_zero_detect<<<NB_N1024, 1024>>>((const unsigned*)ei);
    k_count_deg<<<NB_E256, 256>>>(ei);
    k_scan1<<<NB_N1024, 1024>>>();
    k_scan2<<<1, 256>>>(NB_N1024);
    k_scan3<<<NB_N256, 256>>>();
    k_fill_csr<<<NB_E256, 256>>>(ei);

    const int GEMM_BLKS = (N_NODES + 127) / 128;        // 1563
    const int AGG_BLKS  = (N_NODES * 32 + 255) / 256;   // 25000

    // layer 1: 128 -> 64  (x -> g_h1 -> g_h2)
    k_gemm<128, 64, true><<<GEMM_BLKS, 256>>>(x, W1, N_NODES);
    k_agg64<<<AGG_BLKS, 256>>>(b1);
    // layer 2: 64 -> 64   (g_h2 -> g_h1 -> g_h2)
    k_gemm<64, 64, false><<<GEMM_BLKS, 256>>>(nullptr, W2, N_NODES);
    k_agg64<<<AGG_BLKS, 256>>>(b2);
    // layer 3: 64 -> 32   (g_h2 -> g_h1 -> g_h2)
    k_gemm<64, 32, false><<<GEMM_BLKS, 256>>>(nullptr, W3, N_NODES);
    k_agg32<<<AGG_BLKS, 256>>>(b3);

    // pool + classifier
    k_pool<<<N_GRAPHS / 8, 256>>>(batch, Wc1, bc1, Wc2, bc2, out);
}